// round 6
// baseline (speedup 1.0000x reference)
#include <cuda_runtime.h>
#include <cstdint>
#include <cstddef>

// LowRankINRLayer: out = relu( (x @ v^T) @ W^T )
//   x [16,8192,512] f32, v [16,32,512] f32, W [512,32] f32 -> out f32
//
// Round 6: tf32 mma.sync, 3-stage cp.async pipeline (KC=32), TM=128 rows/CTA,
// 256 threads, 69KB smem + <=85 regs -> 3 CTAs/SM. GEMM2 in 2 passes of 32
// o-cols (W register-resident per pass). v/W pre-converted to tf32 (RNA).

namespace {

constexpr int kB  = 16;
constexpr int kN  = 8192;
constexpr int kDI = 512;
constexpr int kDO = 512;
constexpr int kR  = 32;

constexpr int TM      = 128;          // rows per CTA
constexpr int KC      = 32;           // K per pipeline chunk
constexpr int NCH     = kDI / KC;     // 16
constexpr int STAGES  = 3;
constexpr int THREADS = 256;          // 8 warps

constexpr int XW = KC + 4;                          // 36 words row stride
constexpr int XBUF = TM * XW;                       // 4608 words / stage
constexpr int VBUF = kR * XW;                       // 1152 words / stage
constexpr int V_OFF = STAGES * XBUF;                // 13824
constexpr int SMEM_WORDS = V_OFF + STAGES * VBUF;   // 17280
constexpr int SMEM_BYTES = SMEM_WORDS * 4;          // 69120 B -> 3 CTAs/SM

// tf32(RNA) scratch, filled by prep kernel
__device__ unsigned g_v[kB * kR * kDI];   // blocked [b][ck][n][kk], kk<32
__device__ unsigned g_w[kDO * kR];        // row-major [o][r]

__device__ __forceinline__ unsigned f2tf(float f) {
    unsigned u;
    asm("cvt.rna.tf32.f32 %0, %1;" : "=r"(u) : "f"(f));
    return u;
}

__device__ __forceinline__ void mma_tf32(float& d0, float& d1, float& d2, float& d3,
                                         unsigned a0, unsigned a1, unsigned a2, unsigned a3,
                                         unsigned b0, unsigned b1) {
    asm volatile(
        "mma.sync.aligned.m16n8k8.row.col.f32.tf32.tf32.f32 "
        "{%0,%1,%2,%3}, {%4,%5,%6,%7}, {%8,%9}, {%0,%1,%2,%3};"
        : "+f"(d0), "+f"(d1), "+f"(d2), "+f"(d3)
        : "r"(a0), "r"(a1), "r"(a2), "r"(a3), "r"(b0), "r"(b1));
}

__device__ __forceinline__ void cp16(unsigned dst_smem, const void* src) {
    asm volatile("cp.async.cg.shared.global [%0], [%1], 16;"
                 :: "r"(dst_smem), "l"(src) : "memory");
}

// ---- prep: v -> tf32 RNA blocked [b][ck][n][kk]; W -> tf32 RNA ----
__global__ void prep_kernel(const float* __restrict__ v, const float* __restrict__ W) {
    int idx = blockIdx.x * 256 + threadIdx.x;
    if (idx < kB * kR * kDI) {
        int b = idx >> 14, rem = idx & 16383;
        int n = rem >> 9, k = rem & 511;
        int ck = k >> 5, kk = k & 31;
        g_v[(b << 14) + (ck << 10) + (n << 5) + kk] = f2tf(v[idx]);
    }
    if (idx < kDO * kR) g_w[idx] = f2tf(W[idx]);
}

__global__ void __launch_bounds__(THREADS, 3)
lowrank_kernel(const float* __restrict__ x, float* __restrict__ out)
{
    extern __shared__ unsigned smu[];
    const unsigned sbase = (unsigned)__cvta_generic_to_shared(smu);

    const int tid  = threadIdx.x;
    const int lane = tid & 31;
    const int warp = tid >> 5;
    const int g    = lane >> 2;
    const int t4   = lane & 3;
    const int mw   = warp * 16;

    const int b  = blockIdx.x >> 6;          // 64 tiles per batch
    const int m0 = (blockIdx.x & 63) * TM;

    const float*    xg  = x + ((size_t)b * kN + m0) * kDI;
    const unsigned* gvb = g_v + (size_t)b * (kR * kDI);

    const int vr = tid >> 3, vu = tid & 7;   // v: 256 x 16B units, 1/thread

    auto issue = [&](int c) {
        const int s = c % STAGES;
        const unsigned xd = sbase + (unsigned)(s * XBUF) * 4u;
        #pragma unroll
        for (int i = 0; i < 4; i++) {
            const int q = tid + 256 * i;     // 1024 x 16B units
            const int r = q >> 3, u = q & 7;
            cp16(xd + (unsigned)(r * XW + u * 4) * 4u,
                 xg + (size_t)r * kDI + c * KC + u * 4);
        }
        const unsigned vd = sbase + (unsigned)(V_OFF + s * VBUF) * 4u;
        cp16(vd + (unsigned)(vr * XW + vu * 4) * 4u,
             gvb + c * (kR * KC) + vr * KC + vu * 4);
        asm volatile("cp.async.commit_group;" ::: "memory");
    };

    issue(0); issue(1);

    // ---- GEMM1 mainloop: acc = x_tile @ v^T (per warp: m=16, n=32) ----
    float acc[4][4] = {};

    for (int c = 0; c < NCH; ++c) {
        if (c < NCH - 1) asm volatile("cp.async.wait_group 1;" ::: "memory");
        else             asm volatile("cp.async.wait_group 0;" ::: "memory");
        __syncthreads();   // chunk c ready; chunk c-1 consumed by all warps

        if (c + 2 < NCH) issue(c + 2);   // stage (c-1)%3 is free now

        const float*    xb = (const float*)(smu + (c % STAGES) * XBUF);
        const unsigned* vb = smu + V_OFF + (c % STAGES) * VBUF;

        #pragma unroll
        for (int ks = 0; ks < 4; ks++) {
            const int k0 = ks * 8;
            unsigned a0 = f2tf(xb[(mw + g)     * XW + k0 + t4]);
            unsigned a1 = f2tf(xb[(mw + g + 8) * XW + k0 + t4]);
            unsigned a2 = f2tf(xb[(mw + g)     * XW + k0 + t4 + 4]);
            unsigned a3 = f2tf(xb[(mw + g + 8) * XW + k0 + t4 + 4]);
            #pragma unroll
            for (int nb = 0; nb < 4; nb++) {
                unsigned b0 = vb[(nb * 8 + g) * XW + k0 + t4];
                unsigned b1 = vb[(nb * 8 + g) * XW + k0 + t4 + 4];
                mma_tf32(acc[nb][0], acc[nb][1], acc[nb][2], acc[nb][3],
                         a0, a1, a2, a3, b0, b1);
            }
        }
    }

    // ---- C1 (128x32 f32) -> smem (stage-0 region), stride 36 words ----
    __syncthreads();
    float* c1 = (float*)smu;
    #pragma unroll
    for (int nb = 0; nb < 4; nb++) {
        *reinterpret_cast<float2*>(&c1[(mw + g)     * XW + nb * 8 + 2 * t4]) =
            make_float2(acc[nb][0], acc[nb][1]);
        *reinterpret_cast<float2*>(&c1[(mw + g + 8) * XW + nb * 8 + 2 * t4]) =
            make_float2(acc[nb][2], acc[nb][3]);
    }
    __syncthreads();

    // ---- GEMM2: relu(C1 @ W^T); warp covers o-cols [warp*64, warp*64+64)
    //      in 2 passes of 32 cols (keeps W cache at 32 regs -> 3 CTAs/SM) ----
    float* ob_ = out + ((size_t)b * kN + m0) * kDO;
    #pragma unroll 1
    for (int p = 0; p < 2; p++) {
        const int oc0 = warp * 64 + p * 32;
        unsigned wf[4][4][2];
        #pragma unroll
        for (int ob = 0; ob < 4; ob++) {
            const unsigned* wr = g_w + (size_t)(oc0 + ob * 8 + g) * kR;
            #pragma unroll
            for (int ks = 0; ks < 4; ks++) {
                wf[ob][ks][0] = wr[ks * 8 + t4];
                wf[ob][ks][1] = wr[ks * 8 + t4 + 4];
            }
        }
        #pragma unroll 1
        for (int mb = 0; mb < TM / 16; mb++) {
            const int r0 = mb * 16 + g;
            unsigned a[4][4];
            #pragma unroll
            for (int ks = 0; ks < 4; ks++) {
                a[ks][0] = f2tf(c1[r0       * XW + ks * 8 + t4]);
                a[ks][1] = f2tf(c1[(r0 + 8) * XW + ks * 8 + t4]);
                a[ks][2] = f2tf(c1[r0       * XW + ks * 8 + t4 + 4]);
                a[ks][3] = f2tf(c1[(r0 + 8) * XW + ks * 8 + t4 + 4]);
            }
            #pragma unroll
            for (int ob = 0; ob < 4; ob++) {
                float d0 = 0.f, d1 = 0.f, d2 = 0.f, d3 = 0.f;
                #pragma unroll
                for (int ks = 0; ks < 4; ks++)
                    mma_tf32(d0, d1, d2, d3,
                             a[ks][0], a[ks][1], a[ks][2], a[ks][3],
                             wf[ob][ks][0], wf[ob][ks][1]);
                const int col = oc0 + ob * 8 + 2 * t4;
                *reinterpret_cast<float2*>(&ob_[(size_t)r0 * kDO + col]) =
                    make_float2(fmaxf(d0, 0.f), fmaxf(d1, 0.f));
                *reinterpret_cast<float2*>(&ob_[(size_t)(r0 + 8) * kDO + col]) =
                    make_float2(fmaxf(d2, 0.f), fmaxf(d3, 0.f));
            }
        }
    }
}

} // namespace

extern "C" void kernel_launch(void* const* d_in, const int* in_sizes, int n_in,
                              void* d_out, int out_size) {
    (void)in_sizes; (void)n_in; (void)out_size;
    const float* x = (const float*)d_in[0];
    const float* v = (const float*)d_in[1];
    const float* W = (const float*)d_in[2];
    float* out = (float*)d_out;

    prep_kernel<<<1024, 256>>>(v, W);

    cudaFuncSetAttribute(lowrank_kernel,
                         cudaFuncAttributeMaxDynamicSharedMemorySize, SMEM_BYTES);
    lowrank_kernel<<<kB * (kN / TM), THREADS, SMEM_BYTES>>>(x, out);
}

// round 7
// speedup vs baseline: 1.1183x; 1.1183x over previous
#include <cuda_runtime.h>
#include <cstdint>
#include <cstddef>

// LowRankINRLayer: out = relu( (x @ v^T) @ W^T )
//   x [16,8192,512] f32, v [16,32,512] f32, W [512,32] f32 -> out f32
//
// Round 7: R5 base (tf32 mma.sync, 4-stage cp.async KC=32, TM=128, 256 thr,
// 92KB smem, 2 CTAs/SM, v/W tf32-RNA prepped, W register-resident) plus a
// swizzled warp-private smem-staged epilogue: accumulator fragments are STS'd
// (bank-conflict-free via XOR-8 swizzle), read back linearly, and stored with
// full-line STG.128 (1 wavefront/128B instead of 8 wavefronts per STG.64).

namespace {

constexpr int kB  = 16;
constexpr int kN  = 8192;
constexpr int kDI = 512;
constexpr int kDO = 512;
constexpr int kR  = 32;

constexpr int TM      = 128;          // rows per CTA
constexpr int KC      = 32;           // K per pipeline chunk
constexpr int NCH     = kDI / KC;     // 16
constexpr int STAGES  = 4;
constexpr int THREADS = 256;          // 8 warps

constexpr int XW = KC + 4;                          // 36 words row stride
constexpr int XBUF = TM * XW;                       // 4608 words / stage
constexpr int VBUF = kR * XW;                       // 1152 words / stage
constexpr int V_OFF = STAGES * XBUF;                // 18432
constexpr int SMEM_WORDS = V_OFF + STAGES * VBUF;   // 23040
constexpr int SMEM_BYTES = SMEM_WORDS * 4;          // 92160 B -> 2 CTAs/SM

// epilogue staging: warp-private 16 rows x 64 words, inside stage-1..3 region
constexpr int STG_OFF = XBUF;                       // word 4608 (stage 1 start)
constexpr int STG_PER_WARP = 16 * 64;               // 1024 words (4 KB)

// tf32(RNA) scratch, filled by prep kernel
__device__ unsigned g_v[kB * kR * kDI];   // blocked [b][ck][n][kk], kk<32
__device__ unsigned g_w[kDO * kR];        // row-major [o][r]

__device__ __forceinline__ unsigned f2tf(float f) {
    unsigned u;
    asm("cvt.rna.tf32.f32 %0, %1;" : "=r"(u) : "f"(f));
    return u;
}

__device__ __forceinline__ void mma_tf32(float& d0, float& d1, float& d2, float& d3,
                                         unsigned a0, unsigned a1, unsigned a2, unsigned a3,
                                         unsigned b0, unsigned b1) {
    asm volatile(
        "mma.sync.aligned.m16n8k8.row.col.f32.tf32.tf32.f32 "
        "{%0,%1,%2,%3}, {%4,%5,%6,%7}, {%8,%9}, {%0,%1,%2,%3};"
        : "+f"(d0), "+f"(d1), "+f"(d2), "+f"(d3)
        : "r"(a0), "r"(a1), "r"(a2), "r"(a3), "r"(b0), "r"(b1));
}

__device__ __forceinline__ void cp16(unsigned dst_smem, const void* src) {
    asm volatile("cp.async.cg.shared.global [%0], [%1], 16;"
                 :: "r"(dst_smem), "l"(src) : "memory");
}

// ---- prep: v -> tf32 RNA blocked [b][ck][n][kk]; W -> tf32 RNA ----
__global__ void prep_kernel(const float* __restrict__ v, const float* __restrict__ W) {
    int idx = blockIdx.x * 256 + threadIdx.x;
    if (idx < kB * kR * kDI) {
        int b = idx >> 14, rem = idx & 16383;
        int n = rem >> 9, k = rem & 511;
        int ck = k >> 5, kk = k & 31;
        g_v[(b << 14) + (ck << 10) + (n << 5) + kk] = f2tf(v[idx]);
    }
    if (idx < kDO * kR) g_w[idx] = f2tf(W[idx]);
}

__global__ void __launch_bounds__(THREADS, 2)
lowrank_kernel(const float* __restrict__ x, float* __restrict__ out)
{
    extern __shared__ unsigned smu[];
    const unsigned sbase = (unsigned)__cvta_generic_to_shared(smu);

    const int tid  = threadIdx.x;
    const int lane = tid & 31;
    const int warp = tid >> 5;
    const int g    = lane >> 2;
    const int t4   = lane & 3;
    const int mw   = warp * 16;

    const int b  = blockIdx.x >> 6;          // 64 tiles per batch
    const int m0 = (blockIdx.x & 63) * TM;

    const float*    xg  = x + ((size_t)b * kN + m0) * kDI;
    const unsigned* gvb = g_v + (size_t)b * (kR * kDI);

    const int vr = tid >> 3, vu = tid & 7;   // v: 256 x 16B units, 1/thread

    auto issue = [&](int c) {
        const int s = c & (STAGES - 1);
        const unsigned xd = sbase + (unsigned)(s * XBUF) * 4u;
        #pragma unroll
        for (int i = 0; i < 4; i++) {
            const int q = tid + 256 * i;     // 1024 x 16B units
            const int r = q >> 3, u = q & 7;
            cp16(xd + (unsigned)(r * XW + u * 4) * 4u,
                 xg + (size_t)r * kDI + c * KC + u * 4);
        }
        const unsigned vd = sbase + (unsigned)(V_OFF + s * VBUF) * 4u;
        cp16(vd + (unsigned)(vr * XW + vu * 4) * 4u,
             gvb + c * (kR * KC) + vr * KC + vu * 4);
        asm volatile("cp.async.commit_group;" ::: "memory");
    };

    issue(0); issue(1); issue(2);

    // ---- GEMM1 mainloop: acc = x_tile @ v^T (per warp: m=16, n=32) ----
    float acc[4][4] = {};

    for (int c = 0; c < NCH; ++c) {
        if (c < NCH - 2)        asm volatile("cp.async.wait_group 2;" ::: "memory");
        else if (c == NCH - 2)  asm volatile("cp.async.wait_group 1;" ::: "memory");
        else                    asm volatile("cp.async.wait_group 0;" ::: "memory");
        __syncthreads();   // chunk c ready; chunk c-1 consumed by all warps

        if (c + 3 < NCH) issue(c + 3);   // writes stage (c-1)&3, now free

        const float*    xb = (const float*)(smu + (c & (STAGES - 1)) * XBUF);
        const unsigned* vb = smu + V_OFF + (c & (STAGES - 1)) * VBUF;

        #pragma unroll
        for (int ks = 0; ks < 4; ks++) {
            const int k0 = ks * 8;
            unsigned a0 = f2tf(xb[(mw + g)     * XW + k0 + t4]);
            unsigned a1 = f2tf(xb[(mw + g + 8) * XW + k0 + t4]);
            unsigned a2 = f2tf(xb[(mw + g)     * XW + k0 + t4 + 4]);
            unsigned a3 = f2tf(xb[(mw + g + 8) * XW + k0 + t4 + 4]);
            #pragma unroll
            for (int nb = 0; nb < 4; nb++) {
                unsigned b0 = vb[(nb * 8 + g) * XW + k0 + t4];
                unsigned b1 = vb[(nb * 8 + g) * XW + k0 + t4 + 4];
                mma_tf32(acc[nb][0], acc[nb][1], acc[nb][2], acc[nb][3],
                         a0, a1, a2, a3, b0, b1);
            }
        }
    }

    // ---- C1 (128x32 f32) -> smem (stage-0 region), stride 36 words ----
    __syncthreads();
    float* c1 = (float*)smu;
    #pragma unroll
    for (int nb = 0; nb < 4; nb++) {
        *reinterpret_cast<float2*>(&c1[(mw + g)     * XW + nb * 8 + 2 * t4]) =
            make_float2(acc[nb][0], acc[nb][1]);
        *reinterpret_cast<float2*>(&c1[(mw + g + 8) * XW + nb * 8 + 2 * t4]) =
            make_float2(acc[nb][2], acc[nb][3]);
    }
    __syncthreads();

    // ---- GEMM2: relu(C1 @ W^T); warp owns o-cols [warp*64, warp*64+64) ----
    const int oc0 = warp * 64;
    unsigned wf[8][4][2];
    #pragma unroll
    for (int ob = 0; ob < 8; ob++) {
        const unsigned* wr = g_w + (size_t)(oc0 + ob * 8 + g) * kR;
        #pragma unroll
        for (int ks = 0; ks < 4; ks++) {
            wf[ob][ks][0] = wr[ks * 8 + t4];
            wf[ob][ks][1] = wr[ks * 8 + t4 + 4];
        }
    }

    // warp-private staging buffer: 16 rows x 64 words, XOR-8 swizzled
    float* stg = (float*)smu + STG_OFF + warp * STG_PER_WARP;
    float* ob_ = out + ((size_t)b * kN + m0) * kDO;

    #pragma unroll 1
    for (int mb = 0; mb < TM / 16; mb++) {
        const int r0 = mb * 16 + g;
        unsigned a[4][4];
        #pragma unroll
        for (int ks = 0; ks < 4; ks++) {
            a[ks][0] = f2tf(c1[r0       * XW + ks * 8 + t4]);
            a[ks][1] = f2tf(c1[(r0 + 8) * XW + ks * 8 + t4]);
            a[ks][2] = f2tf(c1[r0       * XW + ks * 8 + t4 + 4]);
            a[ks][3] = f2tf(c1[(r0 + 8) * XW + ks * 8 + t4 + 4]);
        }
        // compute + stage (STS.64, conflict-free under XOR-8 swizzle)
        const int sw = (g & 3) << 3;                 // same for row g and g+8
        #pragma unroll
        for (int ob = 0; ob < 8; ob++) {
            float d0 = 0.f, d1 = 0.f, d2 = 0.f, d3 = 0.f;
            #pragma unroll
            for (int ks = 0; ks < 4; ks++)
                mma_tf32(d0, d1, d2, d3,
                         a[ks][0], a[ks][1], a[ks][2], a[ks][3],
                         wf[ob][ks][0], wf[ob][ks][1]);
            const int lc = (ob * 8 + 2 * t4) ^ sw;   // XOR keeps 2-word alignment
            *reinterpret_cast<float2*>(&stg[g * 64 + lc]) =
                make_float2(fmaxf(d0, 0.f), fmaxf(d1, 0.f));
            *reinterpret_cast<float2*>(&stg[(g + 8) * 64 + lc]) =
                make_float2(fmaxf(d2, 0.f), fmaxf(d3, 0.f));
        }
        __syncwarp();
        // readback (LDS.128, conflict-free) + full-line STG.128
        const int half = lane >> 4;                  // 0/1
        const int colw = (lane & 15) * 4;            // 0..60
        #pragma unroll
        for (int i = 0; i < 8; i++) {
            const int row = 2 * i + half;
            const int sc  = colw ^ ((row & 3) << 3);
            float4 val = *reinterpret_cast<float4*>(&stg[row * 64 + sc]);
            *reinterpret_cast<float4*>(
                &ob_[(size_t)(mb * 16 + row) * kDO + oc0 + colw]) = val;
        }
        __syncwarp();   // staging reused next mb
    }
}

} // namespace

extern "C" void kernel_launch(void* const* d_in, const int* in_sizes, int n_in,
                              void* d_out, int out_size) {
    (void)in_sizes; (void)n_in; (void)out_size;
    const float* x = (const float*)d_in[0];
    const float* v = (const float*)d_in[1];
    const float* W = (const float*)d_in[2];
    float* out = (float*)d_out;

    prep_kernel<<<1024, 256>>>(v, W);

    cudaFuncSetAttribute(lowrank_kernel,
                         cudaFuncAttributeMaxDynamicSharedMemorySize, SMEM_BYTES);
    lowrank_kernel<<<kB * (kN / TM), THREADS, SMEM_BYTES>>>(x, out);
}